// round 1
// baseline (speedup 1.0000x reference)
#include <cuda_runtime.h>
#include <cuda_bf16.h>
#include <math.h>

// ---------------------------------------------------------------------------
// Problem constants
// ---------------------------------------------------------------------------
#define B_   4
#define T_   2048
#define D_   1024
#define H_   16
#define G_   4
#define HD_  64
#define BT_  (B_ * T_)          // 8192

// ---------------------------------------------------------------------------
// Scratch (device globals -- no allocation allowed)
// ---------------------------------------------------------------------------
__device__ float g_q[BT_ * D_];          // [B*T, 1024] = [b,t,h,hd]
__device__ float g_k[BT_ * (G_ * HD_)];  // [B*T, 256]  = [b,t,g,hd]
__device__ float g_v[BT_ * (G_ * HD_)];
__device__ float g_attn[BT_ * D_];       // attention output, [b,t,h,hd]

// ---------------------------------------------------------------------------
// GEMM: C[M,N] = A[M,K] @ B[N,K]^T   (both row-major, K-contiguous)
// BM=BN=128, BK=8, 256 threads, 8x8 per thread.
// M, N, K all divisible by tile sizes for this problem.
// ---------------------------------------------------------------------------
#define GBM 128
#define GBN 128
#define GBK 8

__global__ void __launch_bounds__(256)
gemm_nt(const float* __restrict__ A, const float* __restrict__ Bm,
        float* __restrict__ C, int M, int N, int K)
{
    __shared__ float As[GBK][GBM];
    __shared__ float Bs[GBK][GBN];

    const int tid = threadIdx.x;
    const int m0 = blockIdx.y * GBM;
    const int n0 = blockIdx.x * GBN;
    const int tx = tid & 15;        // 0..15
    const int ty = tid >> 4;        // 0..15

    const int lr = tid >> 1;        // 0..127 (tile row for loads)
    const int lc = (tid & 1) * 4;   // 0 or 4 (k offset)

    float acc[8][8];
#pragma unroll
    for (int i = 0; i < 8; i++)
#pragma unroll
        for (int j = 0; j < 8; j++) acc[i][j] = 0.f;

    const float* Aptr = A + (size_t)(m0 + lr) * K + lc;
    const float* Bptr = Bm + (size_t)(n0 + lr) * K + lc;

    for (int k0 = 0; k0 < K; k0 += GBK) {
        float4 a4 = *(const float4*)(Aptr + k0);
        float4 b4 = *(const float4*)(Bptr + k0);
        As[lc + 0][lr] = a4.x; As[lc + 1][lr] = a4.y;
        As[lc + 2][lr] = a4.z; As[lc + 3][lr] = a4.w;
        Bs[lc + 0][lr] = b4.x; Bs[lc + 1][lr] = b4.y;
        Bs[lc + 2][lr] = b4.z; Bs[lc + 3][lr] = b4.w;
        __syncthreads();

#pragma unroll
        for (int k = 0; k < GBK; k++) {
            float4 a0 = *(const float4*)&As[k][ty * 8];
            float4 a1 = *(const float4*)&As[k][ty * 8 + 4];
            float4 b0 = *(const float4*)&Bs[k][tx * 8];
            float4 b1 = *(const float4*)&Bs[k][tx * 8 + 4];
            float ar[8] = {a0.x, a0.y, a0.z, a0.w, a1.x, a1.y, a1.z, a1.w};
            float br[8] = {b0.x, b0.y, b0.z, b0.w, b1.x, b1.y, b1.z, b1.w};
#pragma unroll
            for (int i = 0; i < 8; i++)
#pragma unroll
                for (int j = 0; j < 8; j++)
                    acc[i][j] = fmaf(ar[i], br[j], acc[i][j]);
        }
        __syncthreads();
    }

#pragma unroll
    for (int i = 0; i < 8; i++) {
        size_t off = (size_t)(m0 + ty * 8 + i) * N + n0 + tx * 8;
        float4 c0 = {acc[i][0], acc[i][1], acc[i][2], acc[i][3]};
        float4 c1 = {acc[i][4], acc[i][5], acc[i][6], acc[i][7]};
        *(float4*)&C[off]     = c0;
        *(float4*)&C[off + 4] = c1;
    }
}

// ---------------------------------------------------------------------------
// RMSNorm (per head-row of 64) + interleaved RoPE, in place.
// buf layout: [B*T, nheads*64]. One warp per (b,t,head) row; lane owns pair
// (2*lane, 2*lane+1). RoPE angle computed in fp64 for safety.
// ---------------------------------------------------------------------------
__global__ void __launch_bounds__(256)
rmsrope_kernel(float* __restrict__ buf, const float* __restrict__ w, int nheads)
{
    const int lane   = threadIdx.x & 31;
    const int warpid = threadIdx.x >> 5;
    const int row    = blockIdx.x * 8 + warpid;   // (b*T + t) * nheads + head
    const int bt     = row / nheads;
    const int head   = row - bt * nheads;
    const int t      = bt & (T_ - 1);

    float* p = buf + (size_t)bt * (nheads * HD_) + head * HD_;
    float2 x = *(float2*)&p[2 * lane];

    float ss = x.x * x.x + x.y * x.y;
#pragma unroll
    for (int o = 16; o > 0; o >>= 1)
        ss += __shfl_xor_sync(0xffffffffu, ss, o);

    float rms = rsqrtf(ss * (1.0f / HD_) + 1e-6f);
    float xn1 = x.x * rms * w[2 * lane];
    float xn2 = x.y * rms * w[2 * lane + 1];

    double inv_freq = pow(10000.0, -(double)lane / 32.0);
    double ang = (double)t * inv_freq;
    float c = (float)cos(ang);
    float s = (float)sin(ang);

    float2 out;
    out.x = xn1 * c - xn2 * s;
    out.y = xn2 * c + xn1 * s;
    *(float2*)&p[2 * lane] = out;
}

// ---------------------------------------------------------------------------
// Causal GQA flash attention, fp32.
// Grid: (T/128, H, B). Block: 128 threads, each owns one query row.
// smem: K tile 64x64, V tile 64x64, S tile 128x65 (padded) = 64.5 KB.
// ---------------------------------------------------------------------------
#define AM   128
#define AN   64
#define SSTR 65

__global__ void __launch_bounds__(128)
attn_kernel(const float* __restrict__ qb, const float* __restrict__ kb,
            const float* __restrict__ vb, float* __restrict__ ob)
{
    extern __shared__ float sm[];
    float* Ks = sm;                    // AN*HD
    float* Vs = sm + AN * HD_;         // AN*HD
    float* Ss = sm + 2 * AN * HD_;     // AM*SSTR

    const int tid = threadIdx.x;
    const int m0  = blockIdx.x * AM;
    const int h   = blockIdx.y;
    const int b   = blockIdx.z;
    const int g   = h >> 2;            // h / (H/G)

    const float* qbase = qb + (size_t)b * T_ * D_ + h * HD_;
    const float* kbase = kb + (size_t)b * T_ * (G_ * HD_) + g * HD_;
    const float* vbase = vb + (size_t)b * T_ * (G_ * HD_) + g * HD_;

    // ---- stage Q tile into Ss (coalesced), then into registers ----
#pragma unroll
    for (int it = 0; it < (AM * HD_ / 4) / 128; it++) {   // 16 iters
        int flat = it * 128 + tid;
        int r  = flat >> 4;
        int c4 = (flat & 15) * 4;
        float4 v4 = *(const float4*)&qbase[(size_t)(m0 + r) * D_ + c4];
        float* d = &Ss[r * SSTR + c4];
        d[0] = v4.x; d[1] = v4.y; d[2] = v4.z; d[3] = v4.w;
    }
    __syncthreads();

    float q[HD_];
    const int row = tid;
#pragma unroll
    for (int d = 0; d < HD_; d++) q[d] = Ss[row * SSTR + d];
    __syncthreads();

    float o[HD_];
#pragma unroll
    for (int d = 0; d < HD_; d++) o[d] = 0.f;
    float mrow = -INFINITY, lrow = 0.f;

    const int nend = m0 + AM;
    for (int n0 = 0; n0 < nend; n0 += AN) {
        // load K,V tiles (coalesced)
#pragma unroll
        for (int it = 0; it < (AN * HD_ / 4) / 128; it++) {   // 8 iters
            int flat = it * 128 + tid;
            int r  = flat >> 4;
            int c4 = (flat & 15) * 4;
            *(float4*)&Ks[r * HD_ + c4] =
                *(const float4*)&kbase[(size_t)(n0 + r) * (G_ * HD_) + c4];
            *(float4*)&Vs[r * HD_ + c4] =
                *(const float4*)&vbase[(size_t)(n0 + r) * (G_ * HD_) + c4];
        }
        __syncthreads();

        // ---- scores for this row ----
        float mt = -INFINITY;
        for (int j = 0; j < AN; j++) {
            float s = 0.f;
#pragma unroll
            for (int d4 = 0; d4 < HD_; d4 += 4) {
                float4 k4 = *(const float4*)&Ks[j * HD_ + d4];
                s = fmaf(q[d4 + 0], k4.x, s);
                s = fmaf(q[d4 + 1], k4.y, s);
                s = fmaf(q[d4 + 2], k4.z, s);
                s = fmaf(q[d4 + 3], k4.w, s);
            }
            s *= 0.125f;                              // 1/sqrt(64)
            if (n0 + j > m0 + row) s = -1e30f;        // causal mask
            mt = fmaxf(mt, s);
            Ss[row * SSTR + j] = s;
        }

        float mnew = fmaxf(mrow, mt);
        float corr = __expf(mrow - mnew);
        lrow *= corr;
#pragma unroll
        for (int d = 0; d < HD_; d++) o[d] *= corr;

        // ---- p = exp(s - mnew), accumulate l and O += P V ----
        for (int j = 0; j < AN; j++) {
            float p = __expf(Ss[row * SSTR + j] - mnew);
            lrow += p;
#pragma unroll
            for (int d4 = 0; d4 < HD_; d4 += 4) {
                float4 v4 = *(const float4*)&Vs[j * HD_ + d4];
                o[d4 + 0] = fmaf(p, v4.x, o[d4 + 0]);
                o[d4 + 1] = fmaf(p, v4.y, o[d4 + 1]);
                o[d4 + 2] = fmaf(p, v4.z, o[d4 + 2]);
                o[d4 + 3] = fmaf(p, v4.w, o[d4 + 3]);
            }
        }
        mrow = mnew;
        __syncthreads();
    }

    const float inv = 1.f / lrow;
    float* optr = ob + (size_t)(b * T_ + m0 + row) * D_ + h * HD_;
#pragma unroll
    for (int d4 = 0; d4 < HD_; d4 += 4) {
        float4 r;
        r.x = o[d4 + 0] * inv; r.y = o[d4 + 1] * inv;
        r.z = o[d4 + 2] * inv; r.w = o[d4 + 3] * inv;
        *(float4*)&optr[d4] = r;
    }
}

// ---------------------------------------------------------------------------
// Launch
// ---------------------------------------------------------------------------
extern "C" void kernel_launch(void* const* d_in, const int* in_sizes, int n_in,
                              void* d_out, int out_size)
{
    const float* x    = (const float*)d_in[0];
    const float* Wq   = (const float*)d_in[1];
    const float* Wk   = (const float*)d_in[2];
    const float* Wv   = (const float*)d_in[3];
    const float* Wo   = (const float*)d_in[4];
    const float* qn_w = (const float*)d_in[5];
    const float* kn_w = (const float*)d_in[6];
    float* out = (float*)d_out;

    float *qp, *kp, *vp, *ap;
    cudaGetSymbolAddress((void**)&qp, g_q);
    cudaGetSymbolAddress((void**)&kp, g_k);
    cudaGetSymbolAddress((void**)&vp, g_v);
    cudaGetSymbolAddress((void**)&ap, g_attn);

    const int smem_attn = (2 * AN * HD_ + AM * SSTR) * sizeof(float); // 66048
    cudaFuncSetAttribute(attn_kernel,
                         cudaFuncAttributeMaxDynamicSharedMemorySize, smem_attn);

    // --- QKV projections ---
    gemm_nt<<<dim3(D_ / GBN, BT_ / GBM), 256>>>(x, Wq, qp, BT_, D_, D_);
    gemm_nt<<<dim3((G_ * HD_) / GBN, BT_ / GBM), 256>>>(x, Wk, kp, BT_, G_ * HD_, D_);
    gemm_nt<<<dim3((G_ * HD_) / GBN, BT_ / GBM), 256>>>(x, Wv, vp, BT_, G_ * HD_, D_);

    // --- RMSNorm + RoPE on q and k ---
    rmsrope_kernel<<<(BT_ * H_) / 8, 256>>>(qp, qn_w, H_);
    rmsrope_kernel<<<(BT_ * G_) / 8, 256>>>(kp, kn_w, G_);

    // --- causal GQA flash attention ---
    attn_kernel<<<dim3(T_ / AM, H_, B_), 128, smem_attn>>>(qp, kp, vp, ap);

    // --- output projection ---
    gemm_nt<<<dim3(D_ / GBN, BT_ / GBM), 256>>>(ap, Wo, out, BT_, D_, D_);
}

// round 3
// speedup vs baseline: 1.4244x; 1.4244x over previous
#include <cuda_runtime.h>
#include <cuda_bf16.h>
#include <math.h>
#include <stdint.h>

// ---------------------------------------------------------------------------
// Problem constants
// ---------------------------------------------------------------------------
#define B_   4
#define T_   2048
#define D_   1024
#define H_   16
#define G_   4
#define HD_  64
#define BT_  (B_ * T_)          // 8192

// ---------------------------------------------------------------------------
// Scratch (device globals -- no allocation allowed)
// ---------------------------------------------------------------------------
__device__ float g_q[BT_ * D_];          // [B*T, 1024] = [b,t,h,hd]
__device__ float g_k[BT_ * (G_ * HD_)];  // [B*T, 256]  = [b,t,g,hd]
__device__ float g_v[BT_ * (G_ * HD_)];
__device__ float g_attn[BT_ * D_];       // attention output, [b,t,h,hd]

// ---------------------------------------------------------------------------
// mma.sync / ldmatrix helpers (base sm_100-legal PTX; no tcgen05)
// ---------------------------------------------------------------------------
__device__ __forceinline__ uint32_t smem_u32(const void* p) {
    uint32_t a;
    asm("{ .reg .u64 t; cvta.to.shared.u64 t, %1; cvt.u32.u64 %0, t; }"
        : "=r"(a) : "l"(p));
    return a;
}

__device__ __forceinline__ void ldsm_x4(uint32_t (&r)[4], uint32_t addr) {
    asm volatile("ldmatrix.sync.aligned.m8n8.x4.shared.b16 {%0,%1,%2,%3}, [%4];"
                 : "=r"(r[0]), "=r"(r[1]), "=r"(r[2]), "=r"(r[3]) : "r"(addr));
}
__device__ __forceinline__ void ldsm_x2(uint32_t (&r)[2], uint32_t addr) {
    asm volatile("ldmatrix.sync.aligned.m8n8.x2.shared.b16 {%0,%1}, [%2];"
                 : "=r"(r[0]), "=r"(r[1]) : "r"(addr));
}

__device__ __forceinline__ void mma_bf16(float (&d)[4], const uint32_t (&a)[4],
                                         const uint32_t (&b)[2]) {
    asm volatile(
        "mma.sync.aligned.m16n8k16.row.col.f32.bf16.bf16.f32 "
        "{%0,%1,%2,%3}, {%4,%5,%6,%7}, {%8,%9}, {%0,%1,%2,%3};"
        : "+f"(d[0]), "+f"(d[1]), "+f"(d[2]), "+f"(d[3])
        : "r"(a[0]), "r"(a[1]), "r"(a[2]), "r"(a[3]), "r"(b[0]), "r"(b[1]));
}

// split fp32x4 into bf16 hi pairs + bf16 residual-lo pairs
__device__ __forceinline__ void split_f4(float4 v, uint32_t& hi0, uint32_t& hi1,
                                         uint32_t& lo0, uint32_t& lo1) {
    __nv_bfloat162 ha = __floats2bfloat162_rn(v.x, v.y);
    __nv_bfloat162 hb = __floats2bfloat162_rn(v.z, v.w);
    float rx = v.x - __bfloat162float(ha.x);
    float ry = v.y - __bfloat162float(ha.y);
    float rz = v.z - __bfloat162float(hb.x);
    float rw = v.w - __bfloat162float(hb.y);
    __nv_bfloat162 la = __floats2bfloat162_rn(rx, ry);
    __nv_bfloat162 lb = __floats2bfloat162_rn(rz, rw);
    hi0 = *(uint32_t*)&ha; hi1 = *(uint32_t*)&hb;
    lo0 = *(uint32_t*)&la; lo1 = *(uint32_t*)&lb;
}

// ---------------------------------------------------------------------------
// Tensor-core GEMM (HMMA): C[M,N] = A[M,K] @ B[N,K]^T (row-major fp32 in/out)
// bf16x3 split. CTA 128x128, K-chunk 32, warp tile 64x32 (2x4 warp grid),
// double-buffered smem, one __syncthreads per chunk.
// ---------------------------------------------------------------------------
#define KC    32
#define LDT   40                    // padded smem stride in bf16 (80 B)
#define TILE_E (128 * LDT)          // 5120 bf16 per tile
#define BUF_E  (4 * TILE_E)         // Ahi, Alo, Bhi, Blo
#define GEMM_SMEM (2 * BUF_E * 2)   // 81920 bytes

__global__ void __launch_bounds__(256, 1)
gemm_mma(const float* __restrict__ A, const float* __restrict__ Bm,
         float* __restrict__ C, int M, int N, int K)
{
    extern __shared__ char smraw[];
    const uint32_t sb = smem_u32(smraw);

    const int tid  = threadIdx.x;
    const int lane = tid & 31;
    const int wid  = tid >> 5;
    const int wm   = wid & 1;       // 0..1  (64 rows each)
    const int wn   = wid >> 1;      // 0..3  (32 cols each)
    const int m0 = blockIdx.y * 128;
    const int n0 = blockIdx.x * 128;

    // global load mapping: each thread owns col (tid&7)*4, rows tid>>3 + it*32
    const int lrow = tid >> 3;
    const int lcol = (tid & 7) * 4;
    const float* pA = A + (size_t)(m0 + lrow) * K + lcol;
    const float* pB = Bm + (size_t)(n0 + lrow) * K + lcol;
    const uint32_t s_elem = (uint32_t)(lrow * LDT + lcol);   // bf16 units

    // ldmatrix fragment addresses (byte offsets within a tile)
    const uint32_t a_off = (uint32_t)(((wm * 64 + (lane & 15)) * LDT
                                       + (lane >> 4) * 8) * 2);
    const uint32_t b_off = (uint32_t)(((wn * 32 + (lane & 7)) * LDT
                                       + ((lane >> 3) & 1) * 8) * 2);

    float acc[4][4][4];
#pragma unroll
    for (int i = 0; i < 4; i++)
#pragma unroll
        for (int j = 0; j < 4; j++)
#pragma unroll
            for (int e = 0; e < 4; e++) acc[i][j][e] = 0.f;

    float4 av[4], bv[4];

    const int nch = K / KC;   // 32

    // ---- prologue: load + store chunk 0 into buffer 0 ----
#pragma unroll
    for (int it = 0; it < 4; it++) {
        av[it] = *(const float4*)(pA + (size_t)it * 32 * K);
        bv[it] = *(const float4*)(pB + (size_t)it * 32 * K);
    }
    {
        const uint32_t base = sb;   // buffer 0
#pragma unroll
        for (int it = 0; it < 4; it++) {
            uint32_t h0, h1, l0, l1;
            uint32_t off = (s_elem + it * 32 * LDT) * 2;
            split_f4(av[it], h0, h1, l0, l1);
            asm volatile("st.shared.v2.b32 [%0], {%1,%2};"
                         :: "r"(base + off), "r"(h0), "r"(h1));
            asm volatile("st.shared.v2.b32 [%0], {%1,%2};"
                         :: "r"(base + TILE_E * 2 + off), "r"(l0), "r"(l1));
            split_f4(bv[it], h0, h1, l0, l1);
            asm volatile("st.shared.v2.b32 [%0], {%1,%2};"
                         :: "r"(base + 2 * TILE_E * 2 + off), "r"(h0), "r"(h1));
            asm volatile("st.shared.v2.b32 [%0], {%1,%2};"
                         :: "r"(base + 3 * TILE_E * 2 + off), "r"(l0), "r"(l1));
        }
    }
    __syncthreads();

    for (int c = 0; c < nch; c++) {
        const int buf = c & 1;
        const uint32_t tb = sb + (uint32_t)buf * (BUF_E * 2);
        const uint32_t aHi = tb;
        const uint32_t aLo = tb + TILE_E * 2;
        const uint32_t bHi = tb + 2 * TILE_E * 2;
        const uint32_t bLo = tb + 3 * TILE_E * 2;

        // issue next chunk's global loads early
        if (c + 1 < nch) {
            const size_t k0 = (size_t)(c + 1) * KC;
#pragma unroll
            for (int it = 0; it < 4; it++) {
                av[it] = *(const float4*)(pA + k0 + (size_t)it * 32 * K);
                bv[it] = *(const float4*)(pB + k0 + (size_t)it * 32 * K);
            }
        }

        // ---- MMAs on current buffer ----
#pragma unroll
        for (int ks = 0; ks < 2; ks++) {
            const uint32_t ksb = ks * 32;   // 16 bf16 = 32 bytes
            uint32_t ahi[4][4], alo[4][4], bhi[4][2], blo[4][2];
#pragma unroll
            for (int mt = 0; mt < 4; mt++) {
                ldsm_x4(ahi[mt], aHi + a_off + mt * (16 * LDT * 2) + ksb);
                ldsm_x4(alo[mt], aLo + a_off + mt * (16 * LDT * 2) + ksb);
            }
#pragma unroll
            for (int nt = 0; nt < 4; nt++) {
                ldsm_x2(bhi[nt], bHi + b_off + nt * (8 * LDT * 2) + ksb);
                ldsm_x2(blo[nt], bLo + b_off + nt * (8 * LDT * 2) + ksb);
            }
#pragma unroll
            for (int mt = 0; mt < 4; mt++)
#pragma unroll
                for (int nt = 0; nt < 4; nt++) {
                    mma_bf16(acc[mt][nt], ahi[mt], bhi[nt]);
                    mma_bf16(acc[mt][nt], ahi[mt], blo[nt]);
                    mma_bf16(acc[mt][nt], alo[mt], bhi[nt]);
                }
        }

        // ---- store next chunk into the other buffer ----
        if (c + 1 < nch) {
            const uint32_t nb = sb + (uint32_t)(buf ^ 1) * (BUF_E * 2);
#pragma unroll
            for (int it = 0; it < 4; it++) {
                uint32_t h0, h1, l0, l1;
                uint32_t off = (s_elem + it * 32 * LDT) * 2;
                split_f4(av[it], h0, h1, l0, l1);
                asm volatile("st.shared.v2.b32 [%0], {%1,%2};"
                             :: "r"(nb + off), "r"(h0), "r"(h1));
                asm volatile("st.shared.v2.b32 [%0], {%1,%2};"
                             :: "r"(nb + TILE_E * 2 + off), "r"(l0), "r"(l1));
                split_f4(bv[it], h0, h1, l0, l1);
                asm volatile("st.shared.v2.b32 [%0], {%1,%2};"
                             :: "r"(nb + 2 * TILE_E * 2 + off), "r"(h0), "r"(h1));
                asm volatile("st.shared.v2.b32 [%0], {%1,%2};"
                             :: "r"(nb + 3 * TILE_E * 2 + off), "r"(l0), "r"(l1));
            }
            __syncthreads();
        }
    }

    // ---- epilogue ----
#pragma unroll
    for (int mt = 0; mt < 4; mt++) {
        const int r0 = m0 + wm * 64 + mt * 16 + (lane >> 2);
#pragma unroll
        for (int nt = 0; nt < 4; nt++) {
            const int cc = n0 + wn * 32 + nt * 8 + (lane & 3) * 2;
            float2 v0 = {acc[mt][nt][0], acc[mt][nt][1]};
            float2 v1 = {acc[mt][nt][2], acc[mt][nt][3]};
            *(float2*)&C[(size_t)r0 * N + cc]       = v0;
            *(float2*)&C[(size_t)(r0 + 8) * N + cc] = v1;
        }
    }
}

// ---------------------------------------------------------------------------
// RMSNorm (per head-row of 64) + interleaved RoPE, in place.
// ---------------------------------------------------------------------------
__global__ void __launch_bounds__(256)
rmsrope_kernel(float* __restrict__ buf, const float* __restrict__ w, int nheads)
{
    const int lane   = threadIdx.x & 31;
    const int warpid = threadIdx.x >> 5;
    const int row    = blockIdx.x * 8 + warpid;
    const int bt     = row / nheads;
    const int head   = row - bt * nheads;
    const int t      = bt & (T_ - 1);

    float* p = buf + (size_t)bt * (nheads * HD_) + head * HD_;
    float2 x = *(float2*)&p[2 * lane];

    float ss = x.x * x.x + x.y * x.y;
#pragma unroll
    for (int o = 16; o > 0; o >>= 1)
        ss += __shfl_xor_sync(0xffffffffu, ss, o);

    float rms = rsqrtf(ss * (1.0f / HD_) + 1e-6f);
    float xn1 = x.x * rms * w[2 * lane];
    float xn2 = x.y * rms * w[2 * lane + 1];

    double inv_freq = pow(10000.0, -(double)lane / 32.0);
    double ang = (double)t * inv_freq;
    float c = (float)cos(ang);
    float s = (float)sin(ang);

    float2 out;
    out.x = xn1 * c - xn2 * s;
    out.y = xn2 * c + xn1 * s;
    *(float2*)&p[2 * lane] = out;
}

// ---------------------------------------------------------------------------
// Causal GQA flash attention, fp32 (unchanged).
// ---------------------------------------------------------------------------
#define AM   128
#define AN   64
#define SSTR 65

__global__ void __launch_bounds__(128)
attn_kernel(const float* __restrict__ qb, const float* __restrict__ kb,
            const float* __restrict__ vb, float* __restrict__ ob)
{
    extern __shared__ float smf[];
    float* Ks = smf;
    float* Vs = smf + AN * HD_;
    float* Ss = smf + 2 * AN * HD_;

    const int tid = threadIdx.x;
    const int m0  = blockIdx.x * AM;
    const int h   = blockIdx.y;
    const int b   = blockIdx.z;
    const int g   = h >> 2;

    const float* qbase = qb + (size_t)b * T_ * D_ + h * HD_;
    const float* kbase = kb + (size_t)b * T_ * (G_ * HD_) + g * HD_;
    const float* vbase = vb + (size_t)b * T_ * (G_ * HD_) + g * HD_;

#pragma unroll
    for (int it = 0; it < (AM * HD_ / 4) / 128; it++) {
        int flat = it * 128 + tid;
        int r  = flat >> 4;
        int c4 = (flat & 15) * 4;
        float4 v4 = *(const float4*)&qbase[(size_t)(m0 + r) * D_ + c4];
        float* d = &Ss[r * SSTR + c4];
        d[0] = v4.x; d[1] = v4.y; d[2] = v4.z; d[3] = v4.w;
    }
    __syncthreads();

    float q[HD_];
    const int row = tid;
#pragma unroll
    for (int d = 0; d < HD_; d++) q[d] = Ss[row * SSTR + d];
    __syncthreads();

    float o[HD_];
#pragma unroll
    for (int d = 0; d < HD_; d++) o[d] = 0.f;
    float mrow = -INFINITY, lrow = 0.f;

    const int nend = m0 + AM;
    for (int n0 = 0; n0 < nend; n0 += AN) {
#pragma unroll
        for (int it = 0; it < (AN * HD_ / 4) / 128; it++) {
            int flat = it * 128 + tid;
            int r  = flat >> 4;
            int c4 = (flat & 15) * 4;
            *(float4*)&Ks[r * HD_ + c4] =
                *(const float4*)&kbase[(size_t)(n0 + r) * (G_ * HD_) + c4];
            *(float4*)&Vs[r * HD_ + c4] =
                *(const float4*)&vbase[(size_t)(n0 + r) * (G_ * HD_) + c4];
        }
        __syncthreads();

        float mt = -INFINITY;
        for (int j = 0; j < AN; j++) {
            float s = 0.f;
#pragma unroll
            for (int d4 = 0; d4 < HD_; d4 += 4) {
                float4 k4 = *(const float4*)&Ks[j * HD_ + d4];
                s = fmaf(q[d4 + 0], k4.x, s);
                s = fmaf(q[d4 + 1], k4.y, s);
                s = fmaf(q[d4 + 2], k4.z, s);
                s = fmaf(q[d4 + 3], k4.w, s);
            }
            s *= 0.125f;
            if (n0 + j > m0 + row) s = -1e30f;
            mt = fmaxf(mt, s);
            Ss[row * SSTR + j] = s;
        }

        float mnew = fmaxf(mrow, mt);
        float corr = __expf(mrow - mnew);
        lrow *= corr;
#pragma unroll
        for (int d = 0; d < HD_; d++) o[d] *= corr;

        for (int j = 0; j < AN; j++) {
            float p = __expf(Ss[row * SSTR + j] - mnew);
            lrow += p;
#pragma unroll
            for (int d4 = 0; d4 < HD_; d4 += 4) {
                float4 v4 = *(const float4*)&Vs[j * HD_ + d4];
                o[d4 + 0] = fmaf(p, v4.x, o[d4 + 0]);
                o[d4 + 1] = fmaf(p, v4.y, o[d4 + 1]);
                o[d4 + 2] = fmaf(p, v4.z, o[d4 + 2]);
                o[d4 + 3] = fmaf(p, v4.w, o[d4 + 3]);
            }
        }
        mrow = mnew;
        __syncthreads();
    }

    const float inv = 1.f / lrow;
    float* optr = ob + (size_t)(b * T_ + m0 + row) * D_ + h * HD_;
#pragma unroll
    for (int d4 = 0; d4 < HD_; d4 += 4) {
        float4 r;
        r.x = o[d4 + 0] * inv; r.y = o[d4 + 1] * inv;
        r.z = o[d4 + 2] * inv; r.w = o[d4 + 3] * inv;
        *(float4*)&optr[d4] = r;
    }
}

// ---------------------------------------------------------------------------
// Launch
// ---------------------------------------------------------------------------
extern "C" void kernel_launch(void* const* d_in, const int* in_sizes, int n_in,
                              void* d_out, int out_size)
{
    const float* x    = (const float*)d_in[0];
    const float* Wq   = (const float*)d_in[1];
    const float* Wk   = (const float*)d_in[2];
    const float* Wv   = (const float*)d_in[3];
    const float* Wo   = (const float*)d_in[4];
    const float* qn_w = (const float*)d_in[5];
    const float* kn_w = (const float*)d_in[6];
    float* out = (float*)d_out;

    float *qp, *kp, *vp, *ap;
    cudaGetSymbolAddress((void**)&qp, g_q);
    cudaGetSymbolAddress((void**)&kp, g_k);
    cudaGetSymbolAddress((void**)&vp, g_v);
    cudaGetSymbolAddress((void**)&ap, g_attn);

    cudaFuncSetAttribute(gemm_mma,
                         cudaFuncAttributeMaxDynamicSharedMemorySize, GEMM_SMEM);
    const int smem_attn = (2 * AN * HD_ + AM * SSTR) * sizeof(float);
    cudaFuncSetAttribute(attn_kernel,
                         cudaFuncAttributeMaxDynamicSharedMemorySize, smem_attn);

    // --- QKV projections (HMMA, bf16x3) ---
    gemm_mma<<<dim3(D_ / 128, BT_ / 128), 256, GEMM_SMEM>>>(x, Wq, qp, BT_, D_, D_);
    gemm_mma<<<dim3((G_ * HD_) / 128, BT_ / 128), 256, GEMM_SMEM>>>(x, Wk, kp, BT_, G_ * HD_, D_);
    gemm_mma<<<dim3((G_ * HD_) / 128, BT_ / 128), 256, GEMM_SMEM>>>(x, Wv, vp, BT_, G_ * HD_, D_);

    // --- RMSNorm + RoPE on q and k ---
    rmsrope_kernel<<<(BT_ * H_) / 8, 256>>>(qp, qn_w, H_);
    rmsrope_kernel<<<(BT_ * G_) / 8, 256>>>(kp, kn_w, G_);

    // --- causal GQA flash attention ---
    attn_kernel<<<dim3(T_ / AM, H_, B_), 128, smem_attn>>>(qp, kp, vp, ap);

    // --- output projection ---
    gemm_mma<<<dim3(D_ / 128, BT_ / 128), 256, GEMM_SMEM>>>(ap, Wo, out, BT_, D_, D_);
}

// round 4
// speedup vs baseline: 3.4493x; 2.4216x over previous
#include <cuda_runtime.h>
#include <cuda_bf16.h>
#include <math.h>
#include <stdint.h>

// ---------------------------------------------------------------------------
// Problem constants
// ---------------------------------------------------------------------------
#define B_   4
#define T_   2048
#define D_   1024
#define H_   16
#define G_   4
#define HD_  64
#define BT_  (B_ * T_)          // 8192

// ---------------------------------------------------------------------------
// Scratch (device globals -- no allocation allowed)
// ---------------------------------------------------------------------------
__device__ float g_q[BT_ * D_];
__device__ float g_k[BT_ * (G_ * HD_)];
__device__ float g_v[BT_ * (G_ * HD_)];
__device__ float g_attn[BT_ * D_];
__device__ __nv_bfloat16 g_qhi[BT_ * D_];
__device__ __nv_bfloat16 g_qlo[BT_ * D_];
__device__ __nv_bfloat16 g_khi[BT_ * G_ * HD_];
__device__ __nv_bfloat16 g_klo[BT_ * G_ * HD_];
__device__ __nv_bfloat16 g_vthi[B_ * G_ * HD_ * T_];   // [b,g,hd,T]
__device__ __nv_bfloat16 g_vtlo[B_ * G_ * HD_ * T_];

// ---------------------------------------------------------------------------
// mma.sync / ldmatrix helpers (base sm_100-legal PTX)
// ---------------------------------------------------------------------------
__device__ __forceinline__ uint32_t smem_u32(const void* p) {
    uint32_t a;
    asm("{ .reg .u64 t; cvta.to.shared.u64 t, %1; cvt.u32.u64 %0, t; }"
        : "=r"(a) : "l"(p));
    return a;
}
__device__ __forceinline__ void ldsm_x4(uint32_t (&r)[4], uint32_t addr) {
    asm volatile("ldmatrix.sync.aligned.m8n8.x4.shared.b16 {%0,%1,%2,%3}, [%4];"
                 : "=r"(r[0]), "=r"(r[1]), "=r"(r[2]), "=r"(r[3]) : "r"(addr));
}
__device__ __forceinline__ void ldsm_x2(uint32_t (&r)[2], uint32_t addr) {
    asm volatile("ldmatrix.sync.aligned.m8n8.x2.shared.b16 {%0,%1}, [%2];"
                 : "=r"(r[0]), "=r"(r[1]) : "r"(addr));
}
__device__ __forceinline__ void mma_bf16(float (&d)[4], const uint32_t (&a)[4],
                                         const uint32_t (&b)[2]) {
    asm volatile(
        "mma.sync.aligned.m16n8k16.row.col.f32.bf16.bf16.f32 "
        "{%0,%1,%2,%3}, {%4,%5,%6,%7}, {%8,%9}, {%0,%1,%2,%3};"
        : "+f"(d[0]), "+f"(d[1]), "+f"(d[2]), "+f"(d[3])
        : "r"(a[0]), "r"(a[1]), "r"(a[2]), "r"(a[3]), "r"(b[0]), "r"(b[1]));
}
__device__ __forceinline__ float ex2(float x) {
    float y;
    asm("ex2.approx.ftz.f32 %0, %1;" : "=f"(y) : "f"(x));
    return y;
}
__device__ __forceinline__ void split_f4(float4 v, uint32_t& hi0, uint32_t& hi1,
                                         uint32_t& lo0, uint32_t& lo1) {
    __nv_bfloat162 ha = __floats2bfloat162_rn(v.x, v.y);
    __nv_bfloat162 hb = __floats2bfloat162_rn(v.z, v.w);
    float rx = v.x - __bfloat162float(ha.x);
    float ry = v.y - __bfloat162float(ha.y);
    float rz = v.z - __bfloat162float(hb.x);
    float rw = v.w - __bfloat162float(hb.y);
    __nv_bfloat162 la = __floats2bfloat162_rn(rx, ry);
    __nv_bfloat162 lb = __floats2bfloat162_rn(rz, rw);
    hi0 = *(uint32_t*)&ha; hi1 = *(uint32_t*)&hb;
    lo0 = *(uint32_t*)&la; lo1 = *(uint32_t*)&lb;
}
__device__ __forceinline__ void packhl(float x, float y, uint32_t& hi, uint32_t& lo) {
    __nv_bfloat162 h = __floats2bfloat162_rn(x, y);
    float lx = x - __bfloat162float(h.x);
    float ly = y - __bfloat162float(h.y);
    __nv_bfloat162 l2 = __floats2bfloat162_rn(lx, ly);
    hi = *(uint32_t*)&h; lo = *(uint32_t*)&l2;
}
#define STS128(addr, v) \
    asm volatile("st.shared.v4.b32 [%0], {%1,%2,%3,%4};" \
                 :: "r"(addr), "r"((v).x), "r"((v).y), "r"((v).z), "r"((v).w))

// ---------------------------------------------------------------------------
// Tensor-core GEMM (HMMA, bf16x3) -- unchanged from round 3 (proven)
// ---------------------------------------------------------------------------
#define KC    32
#define LDT   40
#define TILE_E (128 * LDT)
#define BUF_E  (4 * TILE_E)
#define GEMM_SMEM (2 * BUF_E * 2)

__global__ void __launch_bounds__(256, 1)
gemm_mma(const float* __restrict__ A, const float* __restrict__ Bm,
         float* __restrict__ C, int M, int N, int K)
{
    extern __shared__ char smraw[];
    const uint32_t sb = smem_u32(smraw);

    const int tid  = threadIdx.x;
    const int lane = tid & 31;
    const int wid  = tid >> 5;
    const int wm   = wid & 1;
    const int wn   = wid >> 1;
    const int m0 = blockIdx.y * 128;
    const int n0 = blockIdx.x * 128;

    const int lrow = tid >> 3;
    const int lcol = (tid & 7) * 4;
    const float* pA = A + (size_t)(m0 + lrow) * K + lcol;
    const float* pB = Bm + (size_t)(n0 + lrow) * K + lcol;
    const uint32_t s_elem = (uint32_t)(lrow * LDT + lcol);

    const uint32_t a_off = (uint32_t)(((wm * 64 + (lane & 15)) * LDT
                                       + (lane >> 4) * 8) * 2);
    const uint32_t b_off = (uint32_t)(((wn * 32 + (lane & 7)) * LDT
                                       + ((lane >> 3) & 1) * 8) * 2);

    float acc[4][4][4];
#pragma unroll
    for (int i = 0; i < 4; i++)
#pragma unroll
        for (int j = 0; j < 4; j++)
#pragma unroll
            for (int e = 0; e < 4; e++) acc[i][j][e] = 0.f;

    float4 av[4], bv[4];
    const int nch = K / KC;

#pragma unroll
    for (int it = 0; it < 4; it++) {
        av[it] = *(const float4*)(pA + (size_t)it * 32 * K);
        bv[it] = *(const float4*)(pB + (size_t)it * 32 * K);
    }
    {
        const uint32_t base = sb;
#pragma unroll
        for (int it = 0; it < 4; it++) {
            uint32_t h0, h1, l0, l1;
            uint32_t off = (s_elem + it * 32 * LDT) * 2;
            split_f4(av[it], h0, h1, l0, l1);
            asm volatile("st.shared.v2.b32 [%0], {%1,%2};"
                         :: "r"(base + off), "r"(h0), "r"(h1));
            asm volatile("st.shared.v2.b32 [%0], {%1,%2};"
                         :: "r"(base + TILE_E * 2 + off), "r"(l0), "r"(l1));
            split_f4(bv[it], h0, h1, l0, l1);
            asm volatile("st.shared.v2.b32 [%0], {%1,%2};"
                         :: "r"(base + 2 * TILE_E * 2 + off), "r"(h0), "r"(h1));
            asm volatile("st.shared.v2.b32 [%0], {%1,%2};"
                         :: "r"(base + 3 * TILE_E * 2 + off), "r"(l0), "r"(l1));
        }
    }
    __syncthreads();

    for (int c = 0; c < nch; c++) {
        const int buf = c & 1;
        const uint32_t tb = sb + (uint32_t)buf * (BUF_E * 2);
        const uint32_t aHi = tb;
        const uint32_t aLo = tb + TILE_E * 2;
        const uint32_t bHi = tb + 2 * TILE_E * 2;
        const uint32_t bLo = tb + 3 * TILE_E * 2;

        if (c + 1 < nch) {
            const size_t k0 = (size_t)(c + 1) * KC;
#pragma unroll
            for (int it = 0; it < 4; it++) {
                av[it] = *(const float4*)(pA + k0 + (size_t)it * 32 * K);
                bv[it] = *(const float4*)(pB + k0 + (size_t)it * 32 * K);
            }
        }

#pragma unroll
        for (int ks = 0; ks < 2; ks++) {
            const uint32_t ksb = ks * 32;
            uint32_t ahi[4][4], alo[4][4], bhi[4][2], blo[4][2];
#pragma unroll
            for (int mt = 0; mt < 4; mt++) {
                ldsm_x4(ahi[mt], aHi + a_off + mt * (16 * LDT * 2) + ksb);
                ldsm_x4(alo[mt], aLo + a_off + mt * (16 * LDT * 2) + ksb);
            }
#pragma unroll
            for (int nt = 0; nt < 4; nt++) {
                ldsm_x2(bhi[nt], bHi + b_off + nt * (8 * LDT * 2) + ksb);
                ldsm_x2(blo[nt], bLo + b_off + nt * (8 * LDT * 2) + ksb);
            }
#pragma unroll
            for (int mt = 0; mt < 4; mt++)
#pragma unroll
                for (int nt = 0; nt < 4; nt++) {
                    mma_bf16(acc[mt][nt], ahi[mt], bhi[nt]);
                    mma_bf16(acc[mt][nt], ahi[mt], blo[nt]);
                    mma_bf16(acc[mt][nt], alo[mt], bhi[nt]);
                }
        }

        if (c + 1 < nch) {
            const uint32_t nb = sb + (uint32_t)(buf ^ 1) * (BUF_E * 2);
#pragma unroll
            for (int it = 0; it < 4; it++) {
                uint32_t h0, h1, l0, l1;
                uint32_t off = (s_elem + it * 32 * LDT) * 2;
                split_f4(av[it], h0, h1, l0, l1);
                asm volatile("st.shared.v2.b32 [%0], {%1,%2};"
                             :: "r"(nb + off), "r"(h0), "r"(h1));
                asm volatile("st.shared.v2.b32 [%0], {%1,%2};"
                             :: "r"(nb + TILE_E * 2 + off), "r"(l0), "r"(l1));
                split_f4(bv[it], h0, h1, l0, l1);
                asm volatile("st.shared.v2.b32 [%0], {%1,%2};"
                             :: "r"(nb + 2 * TILE_E * 2 + off), "r"(h0), "r"(h1));
                asm volatile("st.shared.v2.b32 [%0], {%1,%2};"
                             :: "r"(nb + 3 * TILE_E * 2 + off), "r"(l0), "r"(l1));
            }
            __syncthreads();
        }
    }

#pragma unroll
    for (int mt = 0; mt < 4; mt++) {
        const int r0 = m0 + wm * 64 + mt * 16 + (lane >> 2);
#pragma unroll
        for (int nt = 0; nt < 4; nt++) {
            const int cc = n0 + wn * 32 + nt * 8 + (lane & 3) * 2;
            float2 v0 = {acc[mt][nt][0], acc[mt][nt][1]};
            float2 v1 = {acc[mt][nt][2], acc[mt][nt][3]};
            *(float2*)&C[(size_t)r0 * N + cc]       = v0;
            *(float2*)&C[(size_t)(r0 + 8) * N + cc] = v1;
        }
    }
}

// ---------------------------------------------------------------------------
// RMSNorm + RoPE, fp32 in -> bf16 hi/lo out.
// ---------------------------------------------------------------------------
__global__ void __launch_bounds__(256)
rmsrope_bf16(const float* __restrict__ in, const float* __restrict__ w,
             int nheads, __nv_bfloat16* __restrict__ ohi,
             __nv_bfloat16* __restrict__ olo)
{
    const int lane   = threadIdx.x & 31;
    const int warpid = threadIdx.x >> 5;
    const int row    = blockIdx.x * 8 + warpid;
    const int bt     = row / nheads;
    const int head   = row - bt * nheads;
    const int t      = bt & (T_ - 1);

    const float* p = in + (size_t)bt * (nheads * HD_) + head * HD_;
    float2 x = *(const float2*)&p[2 * lane];

    float ss = x.x * x.x + x.y * x.y;
#pragma unroll
    for (int o = 16; o > 0; o >>= 1)
        ss += __shfl_xor_sync(0xffffffffu, ss, o);

    float rms = rsqrtf(ss * (1.0f / HD_) + 1e-6f);
    float xn1 = x.x * rms * w[2 * lane];
    float xn2 = x.y * rms * w[2 * lane + 1];

    double inv_freq = pow(10000.0, -(double)lane / 32.0);
    double ang = (double)t * inv_freq;
    float c = (float)cos(ang);
    float s = (float)sin(ang);

    float ox = xn1 * c - xn2 * s;
    float oy = xn2 * c + xn1 * s;

    const size_t idx = (size_t)bt * (nheads * HD_) + head * HD_ + 2 * lane;
    __nv_bfloat162 h = __floats2bfloat162_rn(ox, oy);
    float lx = ox - __bfloat162float(h.x);
    float ly = oy - __bfloat162float(h.y);
    __nv_bfloat162 l2 = __floats2bfloat162_rn(lx, ly);
    *(__nv_bfloat162*)&ohi[idx] = h;
    *(__nv_bfloat162*)&olo[idx] = l2;
}

// ---------------------------------------------------------------------------
// V convert + transpose: fp32 [b,t,g,hd] -> bf16 hi/lo [b,g,hd,T]
// ---------------------------------------------------------------------------
__global__ void __launch_bounds__(256)
vconv(const float* __restrict__ v, __nv_bfloat16* __restrict__ vth,
      __nv_bfloat16* __restrict__ vtl)
{
    __shared__ float s[64][65];
    const int t0 = blockIdx.x * 64;
    const int g  = blockIdx.y;
    const int b  = blockIdx.z;
    const int tid = threadIdx.x;

#pragma unroll
    for (int it = 0; it < 4; it++) {
        int tr = it * 16 + (tid >> 4);
        int c4 = (tid & 15) * 4;
        float4 val = *(const float4*)&v[((size_t)(b * T_ + t0 + tr) * G_ + g) * HD_ + c4];
        s[tr][c4 + 0] = val.x; s[tr][c4 + 1] = val.y;
        s[tr][c4 + 2] = val.z; s[tr][c4 + 3] = val.w;
    }
    __syncthreads();

    const int hd  = tid >> 2;
    const int seg = tid & 3;
    __nv_bfloat16 hi[16], lo[16];
#pragma unroll
    for (int j = 0; j < 16; j++) {
        float x = s[seg * 16 + j][hd];
        __nv_bfloat16 h = __float2bfloat16(x);
        hi[j] = h;
        lo[j] = __float2bfloat16(x - __bfloat162float(h));
    }
    const size_t ob = ((size_t)(b * G_ + g) * HD_ + hd) * T_ + t0 + seg * 16;
    *(uint4*)&vth[ob]     = *(uint4*)&hi[0];
    *(uint4*)&vth[ob + 8] = *(uint4*)&hi[8];
    *(uint4*)&vtl[ob]     = *(uint4*)&lo[0];
    *(uint4*)&vtl[ob + 8] = *(uint4*)&lo[8];
}

// ---------------------------------------------------------------------------
// Causal GQA flash attention, HMMA bf16x3.
// CTA = 128 q-rows, 8 warps (16 rows each), 64-key tiles.
// ---------------------------------------------------------------------------
#define ASTR  72                       // smem row stride in bf16 (144 B)
#define ATILE (64 * ASTR * 2)          // 9216 B per 64x64 tile array
#define AQT   (128 * ASTR * 2)         // 18432 B per 128x64 Q array
#define ATT_SMEM (2 * AQT + 4 * ATILE) // 73728 B
#define SC_LOG2E 0.18033688011112042f  // 0.125 * log2(e)

__global__ void __launch_bounds__(256)
attn_mma(const __nv_bfloat16* __restrict__ qhi, const __nv_bfloat16* __restrict__ qlo,
         const __nv_bfloat16* __restrict__ khi, const __nv_bfloat16* __restrict__ klo,
         const __nv_bfloat16* __restrict__ vth, const __nv_bfloat16* __restrict__ vtl,
         float* __restrict__ ob)
{
    extern __shared__ char smraw[];
    const uint32_t sb   = smem_u32(smraw);
    const uint32_t sQhi = sb;
    const uint32_t sQlo = sb + AQT;
    const uint32_t sKhi = sb + 2 * AQT;
    const uint32_t sKlo = sKhi + ATILE;
    const uint32_t sVhi = sKlo + ATILE;
    const uint32_t sVlo = sVhi + ATILE;

    const int tid  = threadIdx.x;
    const int lane = tid & 31;
    const int w    = tid >> 5;
    const int mblk = gridDim.x - 1 - blockIdx.x;   // heavy blocks first
    const int m0   = mblk * 128;
    const int h    = blockIdx.y;
    const int b    = blockIdx.z;
    const int g    = h >> 2;

    // ---- stage Q tile, load fragments to registers ----
    {
        const __nv_bfloat16* qh = qhi + ((size_t)(b * T_ + m0) * H_ + h) * HD_;
        const __nv_bfloat16* ql = qlo + ((size_t)(b * T_ + m0) * H_ + h) * HD_;
        const int r = tid >> 3;
        const int c = (tid & 7) * 8;
        const uint32_t soff = (uint32_t)(r * ASTR + c) * 2;
#pragma unroll
        for (int it = 0; it < 4; it++) {
            uint4 a = *(const uint4*)(qh + (size_t)(it * 32 + r) * (H_ * HD_) + c);
            STS128(sQhi + it * 32 * ASTR * 2 + soff, a);
            uint4 bb = *(const uint4*)(ql + (size_t)(it * 32 + r) * (H_ * HD_) + c);
            STS128(sQlo + it * 32 * ASTR * 2 + soff, bb);
        }
    }
    __syncthreads();

    uint32_t qhf[4][4], qlf[4][4];
    {
        const uint32_t a_off = (uint32_t)((w * 16 + (lane & 15)) * ASTR * 2
                                          + (lane >> 4) * 16);
#pragma unroll
        for (int ks = 0; ks < 4; ks++) {
            ldsm_x4(qhf[ks], sQhi + a_off + ks * 32);
            ldsm_x4(qlf[ks], sQlo + a_off + ks * 32);
        }
    }

    float o[8][4];
#pragma unroll
    for (int nt = 0; nt < 8; nt++)
#pragma unroll
        for (int e = 0; e < 4; e++) o[nt][e] = 0.f;
    float mrow[2] = {-INFINITY, -INFINITY};
    float lrow[2] = {0.f, 0.f};

    const __nv_bfloat16* khb = khi + ((size_t)b * T_ * G_ + g) * HD_;
    const __nv_bfloat16* klb = klo + ((size_t)b * T_ * G_ + g) * HD_;
    const __nv_bfloat16* vhb = vth + (size_t)(b * G_ + g) * HD_ * T_;
    const __nv_bfloat16* vlb = vtl + (size_t)(b * G_ + g) * HD_ * T_;

    const int rloc = w * 16 + (lane >> 2);       // local row (first of pair)

    for (int n0 = 0; n0 < m0 + 128; n0 += 64) {
        // ---- load K/V tiles (all threads) ----
        {
            const int r = tid >> 3;              // 0..31
            const int c = (tid & 7) * 8;
            const uint32_t soff = (uint32_t)(r * ASTR + c) * 2;
#pragma unroll
            for (int it = 0; it < 2; it++) {
                const int rr = it * 32 + r;
                const uint32_t so = soff + it * 32 * ASTR * 2;
                uint4 a = *(const uint4*)(khb + (size_t)(n0 + rr) * (G_ * HD_) + c);
                STS128(sKhi + so, a);
                uint4 bb = *(const uint4*)(klb + (size_t)(n0 + rr) * (G_ * HD_) + c);
                STS128(sKlo + so, bb);
                uint4 cc = *(const uint4*)(vhb + (size_t)rr * T_ + n0 + c);
                STS128(sVhi + so, cc);
                uint4 dd = *(const uint4*)(vlb + (size_t)rr * T_ + n0 + c);
                STS128(sVlo + so, dd);
            }
        }
        __syncthreads();

        const bool skip = (n0 > m0 + w * 16 + 15);
        if (!skip) {
            const bool needm = (n0 + 63 > m0 + w * 16);

            // ---- S = Q K^T (bf16x3) ----
            float s[8][4];
#pragma unroll
            for (int nt = 0; nt < 8; nt++) {
#pragma unroll
                for (int e = 0; e < 4; e++) s[nt][e] = 0.f;
                const uint32_t bo = (uint32_t)((nt * 8 + (lane & 7)) * ASTR * 2
                                               + ((lane >> 3) & 1) * 16);
#pragma unroll
                for (int ks = 0; ks < 4; ks++) {
                    uint32_t bh[2], bl[2];
                    ldsm_x2(bh, sKhi + bo + ks * 32);
                    ldsm_x2(bl, sKlo + bo + ks * 32);
                    mma_bf16(s[nt], qhf[ks], bh);
                    mma_bf16(s[nt], qhf[ks], bl);
                    mma_bf16(s[nt], qlf[ks], bh);
                }
            }

            // ---- scale + mask ----
            const int grow0 = m0 + rloc;
            const int grow1 = grow0 + 8;
            float mx0 = -INFINITY, mx1 = -INFINITY;
#pragma unroll
            for (int nt = 0; nt < 8; nt++) {
                const int col = n0 + nt * 8 + (lane & 3) * 2;
#pragma unroll
                for (int e = 0; e < 2; e++) {
                    float v = s[nt][e] * SC_LOG2E;
                    if (needm && (col + e > grow0)) v = -1e30f;
                    s[nt][e] = v;
                    mx0 = fmaxf(mx0, v);
                }
#pragma unroll
                for (int e = 2; e < 4; e++) {
                    float v = s[nt][e] * SC_LOG2E;
                    if (needm && (col + e - 2 > grow1)) v = -1e30f;
                    s[nt][e] = v;
                    mx1 = fmaxf(mx1, v);
                }
            }
            mx0 = fmaxf(mx0, __shfl_xor_sync(0xffffffffu, mx0, 1));
            mx0 = fmaxf(mx0, __shfl_xor_sync(0xffffffffu, mx0, 2));
            mx1 = fmaxf(mx1, __shfl_xor_sync(0xffffffffu, mx1, 1));
            mx1 = fmaxf(mx1, __shfl_xor_sync(0xffffffffu, mx1, 2));

            const float mn0 = fmaxf(mrow[0], mx0);
            const float mn1 = fmaxf(mrow[1], mx1);
            const float c0 = ex2(mrow[0] - mn0);
            const float c1 = ex2(mrow[1] - mn1);
            mrow[0] = mn0; mrow[1] = mn1;

            float s0 = 0.f, s1 = 0.f;
#pragma unroll
            for (int nt = 0; nt < 8; nt++) {
                float p0 = ex2(s[nt][0] - mn0);
                float p1 = ex2(s[nt][1] - mn0);
                float p2 = ex2(s[nt][2] - mn1);
                float p3 = ex2(s[nt][3] - mn1);
                s[nt][0] = p0; s[nt][1] = p1; s[nt][2] = p2; s[nt][3] = p3;
                s0 += p0 + p1; s1 += p2 + p3;
            }
            s0 += __shfl_xor_sync(0xffffffffu, s0, 1);
            s0 += __shfl_xor_sync(0xffffffffu, s0, 2);
            s1 += __shfl_xor_sync(0xffffffffu, s1, 1);
            s1 += __shfl_xor_sync(0xffffffffu, s1, 2);
            lrow[0] = lrow[0] * c0 + s0;
            lrow[1] = lrow[1] * c1 + s1;

#pragma unroll
            for (int nt = 0; nt < 8; nt++) {
                o[nt][0] *= c0; o[nt][1] *= c0;
                o[nt][2] *= c1; o[nt][3] *= c1;
            }

            // ---- P fragments (hi/lo bf16) ----
            uint32_t aph[4][4], apl[4][4];
#pragma unroll
            for (int ks = 0; ks < 4; ks++) {
                packhl(s[2 * ks][0],     s[2 * ks][1],     aph[ks][0], apl[ks][0]);
                packhl(s[2 * ks][2],     s[2 * ks][3],     aph[ks][1], apl[ks][1]);
                packhl(s[2 * ks + 1][0], s[2 * ks + 1][1], aph[ks][2], apl[ks][2]);
                packhl(s[2 * ks + 1][2], s[2 * ks + 1][3], aph[ks][3], apl[ks][3]);
            }

            // ---- O += P V (bf16x3) ----
#pragma unroll
            for (int nt = 0; nt < 8; nt++) {
                const uint32_t bo = (uint32_t)((nt * 8 + (lane & 7)) * ASTR * 2
                                               + ((lane >> 3) & 1) * 16);
#pragma unroll
                for (int ks = 0; ks < 4; ks++) {
                    uint32_t vh[2], vl[2];
                    ldsm_x2(vh, sVhi + bo + ks * 32);
                    ldsm_x2(vl, sVlo + bo + ks * 32);
                    mma_bf16(o[nt], aph[ks], vh);
                    mma_bf16(o[nt], aph[ks], vl);
                    mma_bf16(o[nt], apl[ks], vh);
                }
            }
        }
        __syncthreads();
    }

    // ---- epilogue ----
    const float i0 = 1.f / lrow[0];
    const float i1 = 1.f / lrow[1];
    const int grow = m0 + rloc;
    float* op0 = ob + (size_t)(b * T_ + grow) * D_ + h * HD_ + (lane & 3) * 2;
    float* op1 = op0 + 8 * D_;
#pragma unroll
    for (int nt = 0; nt < 8; nt++) {
        float2 v0 = {o[nt][0] * i0, o[nt][1] * i0};
        float2 v1 = {o[nt][2] * i1, o[nt][3] * i1};
        *(float2*)&op0[nt * 8] = v0;
        *(float2*)&op1[nt * 8] = v1;
    }
}

// ---------------------------------------------------------------------------
// Launch
// ---------------------------------------------------------------------------
extern "C" void kernel_launch(void* const* d_in, const int* in_sizes, int n_in,
                              void* d_out, int out_size)
{
    const float* x    = (const float*)d_in[0];
    const float* Wq   = (const float*)d_in[1];
    const float* Wk   = (const float*)d_in[2];
    const float* Wv   = (const float*)d_in[3];
    const float* Wo   = (const float*)d_in[4];
    const float* qn_w = (const float*)d_in[5];
    const float* kn_w = (const float*)d_in[6];
    float* out = (float*)d_out;

    float *qp, *kp, *vp, *ap;
    __nv_bfloat16 *qhi, *qlo, *khi, *klo, *vthi, *vtlo;
    cudaGetSymbolAddress((void**)&qp, g_q);
    cudaGetSymbolAddress((void**)&kp, g_k);
    cudaGetSymbolAddress((void**)&vp, g_v);
    cudaGetSymbolAddress((void**)&ap, g_attn);
    cudaGetSymbolAddress((void**)&qhi, g_qhi);
    cudaGetSymbolAddress((void**)&qlo, g_qlo);
    cudaGetSymbolAddress((void**)&khi, g_khi);
    cudaGetSymbolAddress((void**)&klo, g_klo);
    cudaGetSymbolAddress((void**)&vthi, g_vthi);
    cudaGetSymbolAddress((void**)&vtlo, g_vtlo);

    cudaFuncSetAttribute(gemm_mma,
                         cudaFuncAttributeMaxDynamicSharedMemorySize, GEMM_SMEM);
    cudaFuncSetAttribute(attn_mma,
                         cudaFuncAttributeMaxDynamicSharedMemorySize, ATT_SMEM);

    // --- QKV projections (HMMA, bf16x3) ---
    gemm_mma<<<dim3(D_ / 128, BT_ / 128), 256, GEMM_SMEM>>>(x, Wq, qp, BT_, D_, D_);
    gemm_mma<<<dim3((G_ * HD_) / 128, BT_ / 128), 256, GEMM_SMEM>>>(x, Wk, kp, BT_, G_ * HD_, D_);
    gemm_mma<<<dim3((G_ * HD_) / 128, BT_ / 128), 256, GEMM_SMEM>>>(x, Wv, vp, BT_, G_ * HD_, D_);

    // --- RMSNorm + RoPE -> bf16 hi/lo; V convert+transpose ---
    rmsrope_bf16<<<(BT_ * H_) / 8, 256>>>(qp, qn_w, H_, qhi, qlo);
    rmsrope_bf16<<<(BT_ * G_) / 8, 256>>>(kp, kn_w, G_, khi, klo);
    vconv<<<dim3(T_ / 64, G_, B_), 256>>>(vp, vthi, vtlo);

    // --- causal GQA flash attention (HMMA) ---
    attn_mma<<<dim3(T_ / 128, H_, B_), 256, ATT_SMEM>>>(qhi, qlo, khi, klo,
                                                        vthi, vtlo, ap);

    // --- output projection ---
    gemm_mma<<<dim3(D_ / 128, BT_ / 128), 256, GEMM_SMEM>>>(ap, Wo, out, BT_, D_, D_);
}